// round 2
// baseline (speedup 1.0000x reference)
#include <cuda_runtime.h>
#include <cuda_bf16.h>

// Problem shape (fixed by reference setup_inputs)
#define NB 4
#define NH 16
#define SQ 2048
#define HD 4
#define WPB 8           // warps (queries) per block

__device__ __forceinline__ float ex2(float x) {
    float r;
    asm("ex2.approx.f32 %0, %1;" : "=f"(r) : "f"(x));
    return r;
}

// scratch out buffer for the (unlikely) attn-only output layout
__device__ float g_scratch_out[(size_t)NB * NH * SQ * HD];

__global__ __launch_bounds__(WPB * 32)
void mha_fwd_kernel(const float* __restrict__ Q,
                    const float* __restrict__ K,
                    const float* __restrict__ V,
                    const int*   __restrict__ M,
                    float* __restrict__ Out,      // [B,H,S,D] (may be null -> scratch)
                    float* __restrict__ Attn,     // [B,H,S,S] (may be null -> skip)
                    int writeAttn)
{
    const int lane = threadIdx.x & 31;
    const int warp = threadIdx.x >> 5;
    const long long gq = (long long)blockIdx.x * WPB + warp;   // global query index over B*H*S
    const int qi = (int)(gq & (SQ - 1));
    const int bh = (int)(gq >> 11);          // gq / SQ
    const int b  = bh >> 4;                  // bh / NH

    const float4* __restrict__ Kv = (const float4*)K + (size_t)bh * SQ;  // SQ float4 rows
    const float4* __restrict__ Vv = (const float4*)V + (size_t)bh * SQ;
    const float4  qv = ((const float4*)Q)[gq];
    const int4*  __restrict__ mrow = (const int4*)(M + ((size_t)b * SQ + qi) * SQ);

    // scale = 1/sqrt(4) = 0.5 ; fold log2(e) so exp(x) = ex2(x * c)
    const float c = 0.72134752044448169f;    // 0.5 * log2(e)

    float p[64];
    float sum = 0.f;
    float ax = 0.f, ay = 0.f, az = 0.f, aw = 0.f;

    #pragma unroll
    for (int i = 0; i < 16; i++) {
        const int g = lane + 32 * i;         // float4-group index (keys 4g..4g+3), coalesced
        const int4 m = mrow[g];
        const float4 k0 = Kv[4*g+0], k1 = Kv[4*g+1], k2 = Kv[4*g+2], k3 = Kv[4*g+3];

        const float s0 = qv.x*k0.x + qv.y*k0.y + qv.z*k0.z + qv.w*k0.w;
        const float s1 = qv.x*k1.x + qv.y*k1.y + qv.z*k1.z + qv.w*k1.w;
        const float s2 = qv.x*k2.x + qv.y*k2.y + qv.z*k2.z + qv.w*k2.w;
        const float s3 = qv.x*k3.x + qv.y*k3.y + qv.z*k3.z + qv.w*k3.w;

        const float p0 = m.x ? ex2(s0 * c) : 0.f;
        const float p1 = m.y ? ex2(s1 * c) : 0.f;
        const float p2 = m.z ? ex2(s2 * c) : 0.f;
        const float p3 = m.w ? ex2(s3 * c) : 0.f;

        const float4 v0 = Vv[4*g+0], v1 = Vv[4*g+1], v2 = Vv[4*g+2], v3 = Vv[4*g+3];

        sum += (p0 + p1) + (p2 + p3);
        ax += p0*v0.x + p1*v1.x + p2*v2.x + p3*v3.x;
        ay += p0*v0.y + p1*v1.y + p2*v2.y + p3*v3.y;
        az += p0*v0.z + p1*v1.z + p2*v2.z + p3*v3.z;
        aw += p0*v0.w + p1*v1.w + p2*v2.w + p3*v3.w;

        p[4*i+0] = p0; p[4*i+1] = p1; p[4*i+2] = p2; p[4*i+3] = p3;
    }

    // warp-reduce the denominator
    #pragma unroll
    for (int off = 16; off; off >>= 1)
        sum += __shfl_xor_sync(0xffffffffu, sum, off);

    if (sum == 0.f) {
        // all-masked row: reference softmax of all -1e9 -> uniform 1/S
        sum = (float)SQ;
        ax = ay = az = aw = 0.f;
        #pragma unroll
        for (int i = 0; i < 16; i++) {
            const int g = lane + 32 * i;
            const float4 v0 = Vv[4*g+0], v1 = Vv[4*g+1], v2 = Vv[4*g+2], v3 = Vv[4*g+3];
            ax += v0.x + v1.x + v2.x + v3.x;
            ay += v0.y + v1.y + v2.y + v3.y;
            az += v0.z + v1.z + v2.z + v3.z;
            aw += v0.w + v1.w + v2.w + v3.w;
            p[4*i+0] = 1.f; p[4*i+1] = 1.f; p[4*i+2] = 1.f; p[4*i+3] = 1.f;
        }
    }

    const float inv = 1.0f / sum;

    if (writeAttn) {
        float4* __restrict__ arow = (float4*)(Attn + (size_t)gq * SQ);
        #pragma unroll
        for (int i = 0; i < 16; i++) {
            const float4 o = make_float4(p[4*i+0] * inv, p[4*i+1] * inv,
                                         p[4*i+2] * inv, p[4*i+3] * inv);
            __stcs(arow + lane + 32 * i, o);   // evict-first: don't pollute L2 (mask lives there)
        }
    }

    // warp-reduce the D=4 accumulator
    #pragma unroll
    for (int off = 16; off; off >>= 1) {
        ax += __shfl_xor_sync(0xffffffffu, ax, off);
        ay += __shfl_xor_sync(0xffffffffu, ay, off);
        az += __shfl_xor_sync(0xffffffffu, az, off);
        aw += __shfl_xor_sync(0xffffffffu, aw, off);
    }
    if (lane == 0) {
        float* o = Out ? Out : g_scratch_out;
        ((float4*)o)[gq] = make_float4(ax * inv, ay * inv, az * inv, aw * inv);
    }
}

extern "C" void kernel_launch(void* const* d_in, const int* in_sizes, int n_in,
                              void* d_out, int out_size)
{
    const float* Q = (const float*)d_in[0];
    const float* K = (const float*)d_in[1];
    const float* V = (const float*)d_in[2];
    const int*   M = (const int*)d_in[3];

    const long long outE  = (long long)NB * NH * SQ * HD;   //    524,288
    const long long attnE = (long long)NB * NH * SQ * SQ;   // 268,435,456

    float* Out  = nullptr;
    float* Attn = nullptr;
    int writeAttn = 0;

    const long long osz = (long long)out_size;
    if (osz >= outE + attnE) {
        // tuple (out, attn) flattened in order
        Out  = (float*)d_out;
        Attn = (float*)d_out + outE;
        writeAttn = 1;
    } else if (osz == attnE) {
        Attn = (float*)d_out;
        writeAttn = 1;
        Out = nullptr;              // kernel falls back to __device__ scratch
    } else {
        Out = (float*)d_out;        // out-only layout
        writeAttn = 0;
    }

    const int blocks = (NB * NH * SQ) / WPB;   // 16384
    mha_fwd_kernel<<<blocks, WPB * 32>>>(Q, K, V, M, Out, Attn, writeAttn);
}

// round 4
// speedup vs baseline: 3.4261x; 3.4261x over previous
#include <cuda_runtime.h>
#include <cuda_bf16.h>

// Problem shape (fixed by reference setup_inputs)
#define NB 4
#define NH 16
#define SQ 2048
#define HD 4
#define WPB 8           // warps (queries) per block

__device__ __forceinline__ float ex2(float x) {
    float r;
    asm("ex2.approx.f32 %0, %1;" : "=f"(r) : "f"(x));
    return r;
}

// scratch buffers for degenerate output layouts
__device__ float g_scratch_out[(size_t)NB * NH * SQ * HD];

__global__ __launch_bounds__(WPB * 32)
void mha_fwd_kernel(const float* __restrict__ Q,
                    const float* __restrict__ K,
                    const float* __restrict__ V,
                    const int*   __restrict__ M,
                    float* __restrict__ Out,      // [B,H,S,D] (never null)
                    float* __restrict__ Attn,     // [B,H,S,S] (may be null -> out-only mode)
                    int writeAttn)
{
    const int lane = threadIdx.x & 31;
    const int warp = threadIdx.x >> 5;
    const long long gq = (long long)blockIdx.x * WPB + warp;   // global query over B*H*S
    const int qi = (int)(gq & (SQ - 1));
    const int bh = (int)(gq >> 11);
    const int b  = bh >> 4;

    const float4* __restrict__ Kv = (const float4*)K + (size_t)bh * SQ;
    const float4* __restrict__ Vv = (const float4*)V + (size_t)bh * SQ;
    const float4  qv = ((const float4*)Q)[gq];
    const int4*  __restrict__ mrow = (const int4*)(M + ((size_t)b * SQ + qi) * SQ);

    float4* __restrict__ arow = writeAttn ? (float4*)(Attn + (size_t)gq * SQ) : nullptr;

    // scale = 1/sqrt(4) = 0.5 ; fold log2(e): exp(x) = ex2(x * c)
    const float c = 0.72134752044448169f;

    float sum = 0.f;
    float ax = 0.f, ay = 0.f, az = 0.f, aw = 0.f;

    // ---- Pass 1: compute p, stream UNNORMALIZED p to attn (L2-cached),
    //              accumulate denominator and p·V. No p kept in registers. ----
    #pragma unroll
    for (int i = 0; i < 16; i++) {
        const int g = lane + 32 * i;                  // coalesced float4-group
        const int4 m = mrow[g];
        const float4 k0 = Kv[4*g+0], k1 = Kv[4*g+1], k2 = Kv[4*g+2], k3 = Kv[4*g+3];

        const float s0 = qv.x*k0.x + qv.y*k0.y + qv.z*k0.z + qv.w*k0.w;
        const float s1 = qv.x*k1.x + qv.y*k1.y + qv.z*k1.z + qv.w*k1.w;
        const float s2 = qv.x*k2.x + qv.y*k2.y + qv.z*k2.z + qv.w*k2.w;
        const float s3 = qv.x*k3.x + qv.y*k3.y + qv.z*k3.z + qv.w*k3.w;

        const float p0 = m.x ? ex2(s0 * c) : 0.f;
        const float p1 = m.y ? ex2(s1 * c) : 0.f;
        const float p2 = m.z ? ex2(s2 * c) : 0.f;
        const float p3 = m.w ? ex2(s3 * c) : 0.f;

        const float4 v0 = Vv[4*g+0], v1 = Vv[4*g+1], v2 = Vv[4*g+2], v3 = Vv[4*g+3];

        sum += (p0 + p1) + (p2 + p3);
        ax += p0*v0.x + p1*v1.x + p2*v2.x + p3*v3.x;
        ay += p0*v0.y + p1*v1.y + p2*v2.y + p3*v3.y;
        az += p0*v0.z + p1*v1.z + p2*v2.z + p3*v3.z;
        aw += p0*v0.w + p1*v1.w + p2*v2.w + p3*v3.w;

        if (writeAttn)
            arow[g] = make_float4(p0, p1, p2, p3);    // L2-cached: read back in pass 2
    }

    // warp-reduce the denominator
    #pragma unroll
    for (int off = 16; off; off >>= 1)
        sum += __shfl_xor_sync(0xffffffffu, sum, off);

    bool uniform = false;
    if (sum == 0.f) {
        // all-masked row: softmax of all -1e9 -> uniform 1/S  (essentially never hit,
        // but must be exact)
        uniform = true;
        sum = (float)SQ;
        ax = ay = az = aw = 0.f;
        #pragma unroll
        for (int i = 0; i < 16; i++) {
            const int g = lane + 32 * i;
            const float4 v0 = Vv[4*g+0], v1 = Vv[4*g+1], v2 = Vv[4*g+2], v3 = Vv[4*g+3];
            ax += v0.x + v1.x + v2.x + v3.x;
            ay += v0.y + v1.y + v2.y + v3.y;
            az += v0.z + v1.z + v2.z + v3.z;
            aw += v0.w + v1.w + v2.w + v3.w;
        }
    }

    const float inv = 1.0f / sum;

    // ---- Pass 2: read own row back (same thread, same addresses -> ordered;
    //              still in L1/L2), normalize, final evict-first store. ----
    if (writeAttn) {
        if (!uniform) {
            #pragma unroll
            for (int i = 0; i < 16; i++) {
                const int g = lane + 32 * i;
                float4 t = arow[g];
                t.x *= inv; t.y *= inv; t.z *= inv; t.w *= inv;
                __stcs(arow + g, t);
            }
        } else {
            const float4 u = make_float4(inv, inv, inv, inv);
            #pragma unroll
            for (int i = 0; i < 16; i++)
                __stcs(arow + lane + 32 * i, u);
        }
    }

    // warp-reduce the D=4 accumulator
    #pragma unroll
    for (int off = 16; off; off >>= 1) {
        ax += __shfl_xor_sync(0xffffffffu, ax, off);
        ay += __shfl_xor_sync(0xffffffffu, ay, off);
        az += __shfl_xor_sync(0xffffffffu, az, off);
        aw += __shfl_xor_sync(0xffffffffu, aw, off);
    }
    if (lane == 0)
        ((float4*)Out)[gq] = make_float4(ax * inv, ay * inv, az * inv, aw * inv);
}

extern "C" void kernel_launch(void* const* d_in, const int* in_sizes, int n_in,
                              void* d_out, int out_size)
{
    const float* Q = (const float*)d_in[0];
    const float* K = (const float*)d_in[1];
    const float* V = (const float*)d_in[2];
    const int*   M = (const int*)d_in[3];

    const long long outE  = (long long)NB * NH * SQ * HD;   //    524,288
    const long long attnE = (long long)NB * NH * SQ * SQ;   // 268,435,456

    float* Out  = nullptr;
    float* Attn = nullptr;
    int writeAttn = 0;

    const long long osz = (long long)out_size;
    if (osz >= outE + attnE) {
        Out  = (float*)d_out;           // tuple (out, attn) flattened in order
        Attn = (float*)d_out + outE;
        writeAttn = 1;
    } else if (osz == attnE) {
        Attn = (float*)d_out;
        writeAttn = 1;
        Out = g_scratch_out;
    } else {
        Out = (float*)d_out;
        writeAttn = 0;
    }

    const int blocks = (NB * NH * SQ) / WPB;   // 16384
    mha_fwd_kernel<<<blocks, WPB * 32>>>(Q, K, V, M, Out, Attn, writeAttn);
}

// round 5
// speedup vs baseline: 7.9388x; 2.3172x over previous
#include <cuda_runtime.h>
#include <cuda_bf16.h>

// Problem shape (fixed by reference setup_inputs)
#define NB 4
#define NH 16
#define SQ 2048
#define HD 4
#define WPB 8           // warps per block
#define QPB 4           // queries per block (share K/V across these)

__device__ __forceinline__ float ex2(float x) {
    float r;
    asm("ex2.approx.f32 %0, %1;" : "=f"(r) : "f"(x));
    return r;
}

__device__ float g_scratch_out[(size_t)NB * NH * SQ * HD];

__global__ __launch_bounds__(WPB * 32, 2)
void mha_fwd_kernel(const float* __restrict__ Q,
                    const float* __restrict__ K,
                    const float* __restrict__ V,
                    const int*   __restrict__ M,
                    float* __restrict__ Out,      // never null (scratch fallback)
                    float* __restrict__ Attn,     // may be null -> out-only
                    int writeAttn)
{
    const int lane = threadIdx.x & 31;
    const int warp = threadIdx.x >> 5;
    const int q0g  = blockIdx.x * QPB;           // global query base (B*H*S space)
    const int bh   = q0g >> 11;                  // / SQ  (QPB divides SQ -> same bh)
    const int b    = bh >> 4;                    // / NH
    const int qi0  = q0g & (SQ - 1);

    const float4* __restrict__ Kv = (const float4*)K + (size_t)bh * SQ;
    const float4* __restrict__ Vv = (const float4*)V + (size_t)bh * SQ;
    const int4*   __restrict__ Mb = (const int4*)(M + ((size_t)b * SQ + qi0) * SQ);
    // mask row stride in int4 units:
    const int MROW = SQ / 4;                     // 512

    // q pre-scaled by 0.5*log2(e): exp(0.5*s) == ex2(dot(qc,k))
    const float c = 0.72134752044448169f;
    float4 qc[QPB];
    #pragma unroll
    for (int q = 0; q < QPB; q++) {
        float4 t = ((const float4*)Q)[q0g + q];
        qc[q] = make_float4(t.x * c, t.y * c, t.z * c, t.w * c);
    }

    // each warp owns keys [warp*256, warp*256+256); lane owns 8 keys
    // (2 mask-groups of 4 consecutive keys)
    float p[QPB][2][4];
    float sum[QPB], ax[QPB], ay[QPB], az[QPB], aw[QPB];
    #pragma unroll
    for (int q = 0; q < QPB; q++) { sum[q]=0.f; ax[q]=0.f; ay[q]=0.f; az[q]=0.f; aw[q]=0.f; }

    #pragma unroll
    for (int j = 0; j < 2; j++) {
        const int mg = warp * 64 + lane + 32 * j;   // mask-group: keys 4mg..4mg+3 (coalesced)
        int4 m[QPB];
        #pragma unroll
        for (int q = 0; q < QPB; q++) m[q] = Mb[q * MROW + mg];

        #pragma unroll
        for (int t = 0; t < 4; t++) {
            const float4 k = Kv[4 * mg + t];
            const float4 v = Vv[4 * mg + t];
            #pragma unroll
            for (int q = 0; q < QPB; q++) {
                const float s = qc[q].x*k.x + qc[q].y*k.y + qc[q].z*k.z + qc[q].w*k.w;
                const int mm = (t == 0) ? m[q].x : (t == 1) ? m[q].y
                             : (t == 2) ? m[q].z : m[q].w;
                const float pp = mm ? ex2(s) : 0.f;
                sum[q] += pp;
                ax[q] += pp * v.x; ay[q] += pp * v.y;
                az[q] += pp * v.z; aw[q] += pp * v.w;
                p[q][j][t] = pp;
            }
        }
    }

    // ---- reduction: warp-level, then cross-warp via smem ----
    __shared__ float part[WPB][QPB][5];
    __shared__ float sinv[QPB];
    __shared__ int   sflag[QPB];

    #pragma unroll
    for (int q = 0; q < QPB; q++) {
        float v0 = sum[q], v1 = ax[q], v2 = ay[q], v3 = az[q], v4 = aw[q];
        #pragma unroll
        for (int off = 16; off; off >>= 1) {
            v0 += __shfl_xor_sync(0xffffffffu, v0, off);
            v1 += __shfl_xor_sync(0xffffffffu, v1, off);
            v2 += __shfl_xor_sync(0xffffffffu, v2, off);
            v3 += __shfl_xor_sync(0xffffffffu, v3, off);
            v4 += __shfl_xor_sync(0xffffffffu, v4, off);
        }
        if (lane == 0) {
            part[warp][q][0] = v0; part[warp][q][1] = v1; part[warp][q][2] = v2;
            part[warp][q][3] = v3; part[warp][q][4] = v4;
        }
    }
    __syncthreads();

    if (threadIdx.x < QPB) {
        const int q = threadIdx.x;
        float s = 0.f, x = 0.f, y = 0.f, z = 0.f, w = 0.f;
        #pragma unroll
        for (int wp = 0; wp < WPB; wp++) {
            s += part[wp][q][0]; x += part[wp][q][1]; y += part[wp][q][2];
            z += part[wp][q][3]; w += part[wp][q][4];
        }
        const int flag = (s == 0.f);                 // all-masked row (softmax of -1e9 -> uniform)
        const float inv = 1.0f / (flag ? (float)SQ : s);
        sinv[q] = inv; sflag[q] = flag;
        if (!flag)
            ((float4*)Out)[q0g + q] = make_float4(x*inv, y*inv, z*inv, w*inv);
    }
    __syncthreads();

    // ---- degenerate all-masked rows (block-uniform cold path) ----
    int any = 0;
    #pragma unroll
    for (int q = 0; q < QPB; q++) any |= sflag[q];
    if (any) {
        #pragma unroll
        for (int q = 0; q < QPB; q++) {
            if (sflag[q]) {
                float x = 0.f, y = 0.f, z = 0.f, w = 0.f;
                #pragma unroll
                for (int j = 0; j < 2; j++) {
                    const int mg = warp * 64 + lane + 32 * j;
                    #pragma unroll
                    for (int t = 0; t < 4; t++) {
                        const float4 v = Vv[4 * mg + t];
                        x += v.x; y += v.y; z += v.z; w += v.w;
                    }
                }
                #pragma unroll
                for (int off = 16; off; off >>= 1) {
                    x += __shfl_xor_sync(0xffffffffu, x, off);
                    y += __shfl_xor_sync(0xffffffffu, y, off);
                    z += __shfl_xor_sync(0xffffffffu, z, off);
                    w += __shfl_xor_sync(0xffffffffu, w, off);
                }
                if (lane == 0) {
                    part[warp][q][1] = x; part[warp][q][2] = y;
                    part[warp][q][3] = z; part[warp][q][4] = w;
                }
            }
        }
        __syncthreads();
        if (threadIdx.x < QPB && sflag[threadIdx.x]) {
            const int q = threadIdx.x;
            float x = 0.f, y = 0.f, z = 0.f, w = 0.f;
            #pragma unroll
            for (int wp = 0; wp < WPB; wp++) {
                x += part[wp][q][1]; y += part[wp][q][2];
                z += part[wp][q][3]; w += part[wp][q][4];
            }
            const float inv = sinv[q];
            ((float4*)Out)[q0g + q] = make_float4(x*inv, y*inv, z*inv, w*inv);
        }
    }

    // ---- single normalized attn write (evict-first; keep mask in L2) ----
    if (writeAttn) {
        #pragma unroll
        for (int q = 0; q < QPB; q++) {
            float4* __restrict__ arow = (float4*)(Attn + (size_t)(q0g + q) * SQ);
            const float inv = sinv[q];
            if (!sflag[q]) {
                #pragma unroll
                for (int j = 0; j < 2; j++) {
                    const int mg = warp * 64 + lane + 32 * j;
                    __stcs(arow + mg, make_float4(p[q][j][0]*inv, p[q][j][1]*inv,
                                                  p[q][j][2]*inv, p[q][j][3]*inv));
                }
            } else {
                const float4 u = make_float4(inv, inv, inv, inv);
                #pragma unroll
                for (int j = 0; j < 2; j++)
                    __stcs(arow + warp * 64 + lane + 32 * j, u);
            }
        }
    }
}

extern "C" void kernel_launch(void* const* d_in, const int* in_sizes, int n_in,
                              void* d_out, int out_size)
{
    const float* Q = (const float*)d_in[0];
    const float* K = (const float*)d_in[1];
    const float* V = (const float*)d_in[2];
    const int*   M = (const int*)d_in[3];

    const long long outE  = (long long)NB * NH * SQ * HD;   //    524,288
    const long long attnE = (long long)NB * NH * SQ * SQ;   // 268,435,456

    float* Out  = nullptr;
    float* Attn = nullptr;
    int writeAttn = 0;

    const long long osz = (long long)out_size;
    if (osz >= outE + attnE) {
        Out  = (float*)d_out;           // tuple (out, attn) flattened in order
        Attn = (float*)d_out + outE;
        writeAttn = 1;
    } else if (osz == attnE) {
        Attn = (float*)d_out;
        writeAttn = 1;
        Out = g_scratch_out;
    } else {
        Out = (float*)d_out;
        writeAttn = 0;
    }

    const int blocks = (NB * NH * SQ) / QPB;   // 32768
    mha_fwd_kernel<<<blocks, WPB * 32>>>(Q, K, V, M, Out, Attn, writeAttn);
}

// round 6
// speedup vs baseline: 8.8536x; 1.1152x over previous
#include <cuda_runtime.h>
#include <cuda_bf16.h>

// Problem shape (fixed by reference setup_inputs)
#define NB 4
#define NH 16
#define SQ 2048
#define HD 4
#define WPB 8           // warps per block
#define QPB 4           // queries per block (share K/V)
#define KPL 8           // keys per lane (stride-32 within warp slice)

__device__ __forceinline__ float ex2(float x) {
    float r;
    asm("ex2.approx.f32 %0, %1;" : "=f"(r) : "f"(x));
    return r;
}

__device__ float g_scratch_out[(size_t)NB * NH * SQ * HD];

__global__ __launch_bounds__(WPB * 32, 3)
void mha_fwd_kernel(const float* __restrict__ Q,
                    const float* __restrict__ K,
                    const float* __restrict__ V,
                    const int*   __restrict__ M,
                    float* __restrict__ Out,      // never null (scratch fallback)
                    float* __restrict__ Attn,     // may be null -> out-only
                    int writeAttn)
{
    const int lane = threadIdx.x & 31;
    const int warp = threadIdx.x >> 5;
    const int q0g  = blockIdx.x * QPB;           // base query in B*H*S space
    const int bh   = q0g >> 11;
    const int b    = bh >> 4;
    const int qi0  = q0g & (SQ - 1);

    const float4* __restrict__ Kv = (const float4*)K + (size_t)bh * SQ;
    const float4* __restrict__ Vv = (const float4*)V + (size_t)bh * SQ;
    const int*    __restrict__ Mb = M + ((size_t)b * SQ + qi0) * SQ;

    // q pre-scaled by 0.5*log2(e): exp(0.5*s) == ex2(dot(qc,k))
    const float c = 0.72134752044448169f;
    float4 qc[QPB];
    #pragma unroll
    for (int q = 0; q < QPB; q++) {
        float4 t = ((const float4*)Q)[q0g + q];
        qc[q] = make_float4(t.x * c, t.y * c, t.z * c, t.w * c);
    }

    __shared__ float part[WPB][QPB][4];
    __shared__ float sinv[QPB];
    __shared__ int   sflag[QPB];

    // ---- Pass 1: p = exp(score) (masked), row sums. Lane owns keys
    //      warp*256 + u*32 + lane  -> every load fully coalesced. ----
    float p[QPB][KPL];
    float sum0 = 0.f, sum1 = 0.f, sum2 = 0.f, sum3 = 0.f;

    #pragma unroll
    for (int u = 0; u < KPL; u++) {
        const int kk = warp * 256 + u * 32 + lane;
        const float4 k = Kv[kk];
        const int m0 = Mb[0 * SQ + kk];
        const int m1 = Mb[1 * SQ + kk];
        const int m2 = Mb[2 * SQ + kk];
        const int m3 = Mb[3 * SQ + kk];

        const float s0 = qc[0].x*k.x + qc[0].y*k.y + qc[0].z*k.z + qc[0].w*k.w;
        const float s1 = qc[1].x*k.x + qc[1].y*k.y + qc[1].z*k.z + qc[1].w*k.w;
        const float s2 = qc[2].x*k.x + qc[2].y*k.y + qc[2].z*k.z + qc[2].w*k.w;
        const float s3 = qc[3].x*k.x + qc[3].y*k.y + qc[3].z*k.z + qc[3].w*k.w;

        const float p0 = m0 ? ex2(s0) : 0.f;
        const float p1 = m1 ? ex2(s1) : 0.f;
        const float p2 = m2 ? ex2(s2) : 0.f;
        const float p3 = m3 ? ex2(s3) : 0.f;

        sum0 += p0; sum1 += p1; sum2 += p2; sum3 += p3;
        p[0][u] = p0; p[1][u] = p1; p[2][u] = p2; p[3][u] = p3;
    }

    // warp-reduce sums, cross-warp via smem
    #pragma unroll
    for (int off = 16; off; off >>= 1) {
        sum0 += __shfl_xor_sync(0xffffffffu, sum0, off);
        sum1 += __shfl_xor_sync(0xffffffffu, sum1, off);
        sum2 += __shfl_xor_sync(0xffffffffu, sum2, off);
        sum3 += __shfl_xor_sync(0xffffffffu, sum3, off);
    }
    if (lane == 0) {
        part[warp][0][0] = sum0; part[warp][1][0] = sum1;
        part[warp][2][0] = sum2; part[warp][3][0] = sum3;
    }
    __syncthreads();

    if (threadIdx.x < QPB) {
        const int q = threadIdx.x;
        float s = 0.f;
        #pragma unroll
        for (int wp = 0; wp < WPB; wp++) s += part[wp][q][0];
        const int flag = (s == 0.f);          // all-masked row -> uniform softmax
        sinv[q]  = 1.0f / (flag ? (float)SQ : s);
        sflag[q] = flag;
    }
    __syncthreads();

    float inv[QPB];
    #pragma unroll
    for (int q = 0; q < QPB; q++) {
        inv[q] = sinv[q];
        if (sflag[q]) {                        // uniform row: p := 1 everywhere
            #pragma unroll
            for (int u = 0; u < KPL; u++) p[q][u] = 1.f;
        }
    }

    // ---- Pass 2: normalize, store attn (evict-first), accumulate out ----
    float ax0=0.f, ay0=0.f, az0=0.f, aw0=0.f;
    float ax1=0.f, ay1=0.f, az1=0.f, aw1=0.f;
    float ax2=0.f, ay2=0.f, az2=0.f, aw2=0.f;
    float ax3=0.f, ay3=0.f, az3=0.f, aw3=0.f;

    #pragma unroll
    for (int u = 0; u < KPL; u++) {
        const int kk = warp * 256 + u * 32 + lane;
        const float4 v = Vv[kk];

        const float n0 = p[0][u] * inv[0];
        const float n1 = p[1][u] * inv[1];
        const float n2 = p[2][u] * inv[2];
        const float n3 = p[3][u] * inv[3];

        if (writeAttn) {
            __stcs(Attn + (size_t)(q0g + 0) * SQ + kk, n0);
            __stcs(Attn + (size_t)(q0g + 1) * SQ + kk, n1);
            __stcs(Attn + (size_t)(q0g + 2) * SQ + kk, n2);
            __stcs(Attn + (size_t)(q0g + 3) * SQ + kk, n3);
        }

        ax0 += n0*v.x; ay0 += n0*v.y; az0 += n0*v.z; aw0 += n0*v.w;
        ax1 += n1*v.x; ay1 += n1*v.y; az1 += n1*v.z; aw1 += n1*v.w;
        ax2 += n2*v.x; ay2 += n2*v.y; az2 += n2*v.z; aw2 += n2*v.w;
        ax3 += n3*v.x; ay3 += n3*v.y; az3 += n3*v.z; aw3 += n3*v.w;
    }

    // warp-reduce the out accumulators, cross-warp via smem
    #pragma unroll
    for (int off = 16; off; off >>= 1) {
        ax0 += __shfl_xor_sync(0xffffffffu, ax0, off);
        ay0 += __shfl_xor_sync(0xffffffffu, ay0, off);
        az0 += __shfl_xor_sync(0xffffffffu, az0, off);
        aw0 += __shfl_xor_sync(0xffffffffu, aw0, off);
        ax1 += __shfl_xor_sync(0xffffffffu, ax1, off);
        ay1 += __shfl_xor_sync(0xffffffffu, ay1, off);
        az1 += __shfl_xor_sync(0xffffffffu, az1, off);
        aw1 += __shfl_xor_sync(0xffffffffu, aw1, off);
        ax2 += __shfl_xor_sync(0xffffffffu, ax2, off);
        ay2 += __shfl_xor_sync(0xffffffffu, ay2, off);
        az2 += __shfl_xor_sync(0xffffffffu, az2, off);
        aw2 += __shfl_xor_sync(0xffffffffu, aw2, off);
        ax3 += __shfl_xor_sync(0xffffffffu, ax3, off);
        ay3 += __shfl_xor_sync(0xffffffffu, ay3, off);
        az3 += __shfl_xor_sync(0xffffffffu, az3, off);
        aw3 += __shfl_xor_sync(0xffffffffu, aw3, off);
    }
    __syncthreads();           // reuse part[]
    if (lane == 0) {
        part[warp][0][0]=ax0; part[warp][0][1]=ay0; part[warp][0][2]=az0; part[warp][0][3]=aw0;
        part[warp][1][0]=ax1; part[warp][1][1]=ay1; part[warp][1][2]=az1; part[warp][1][3]=aw1;
        part[warp][2][0]=ax2; part[warp][2][1]=ay2; part[warp][2][2]=az2; part[warp][2][3]=aw2;
        part[warp][3][0]=ax3; part[warp][3][1]=ay3; part[warp][3][2]=az3; part[warp][3][3]=aw3;
    }
    __syncthreads();

    if (threadIdx.x < QPB) {
        const int q = threadIdx.x;
        float x=0.f, y=0.f, z=0.f, w=0.f;
        #pragma unroll
        for (int wp = 0; wp < WPB; wp++) {
            x += part[wp][q][0]; y += part[wp][q][1];
            z += part[wp][q][2]; w += part[wp][q][3];
        }
        ((float4*)Out)[q0g + q] = make_float4(x, y, z, w);
    }
}

extern "C" void kernel_launch(void* const* d_in, const int* in_sizes, int n_in,
                              void* d_out, int out_size)
{
    const float* Q = (const float*)d_in[0];
    const float* K = (const float*)d_in[1];
    const float* V = (const float*)d_in[2];
    const int*   M = (const int*)d_in[3];

    const long long outE  = (long long)NB * NH * SQ * HD;   //    524,288
    const long long attnE = (long long)NB * NH * SQ * SQ;   // 268,435,456

    float* Out  = nullptr;
    float* Attn = nullptr;
    int writeAttn = 0;

    const long long osz = (long long)out_size;
    if (osz >= outE + attnE) {
        Out  = (float*)d_out;           // tuple (out, attn) flattened in order
        Attn = (float*)d_out + outE;
        writeAttn = 1;
    } else if (osz == attnE) {
        Attn = (float*)d_out;
        writeAttn = 1;
        Out = g_scratch_out;
    } else {
        Out = (float*)d_out;
        writeAttn = 0;
    }

    const int blocks = (NB * NH * SQ) / QPB;   // 32768
    mha_fwd_kernel<<<blocks, WPB * 32>>>(Q, K, V, M, Out, Attn, writeAttn);
}